// round 15
// baseline (speedup 1.0000x reference)
#include <cuda_runtime.h>

#define UP      4096
#define HALF    2048
#define QUART   1024
#define NB      32
#define NA      256
#define SIGL    2048
#define N1      1024
#define THREADS 512
#define OUT_ELEMS (NB * NA * SIGL)
#define IDX(i) ((i) + ((i) >> 3))   // word-granular pad (SoA): odd lane strides

// Forward-FFT results: (32, 4096) complex64, natural order. 1 MB static scratch.
__device__ float2 g_xh[NB * UP];

__device__ __forceinline__ float2 cmul(float2 a, float2 b) {
    return make_float2(a.x * b.x - a.y * b.y, a.x * b.y + a.y * b.x);
}
__device__ __forceinline__ float2 cadd(float2 a, float2 b) { return make_float2(a.x + b.x, a.y + b.y); }
__device__ __forceinline__ float2 csub(float2 a, float2 b) { return make_float2(a.x - b.x, a.y - b.y); }
__device__ __forceinline__ float2 muli(float2 a)  { return make_float2(-a.y, a.x); }

// twq[k] = e^{+2*pi*i*k/4096}, k in [0,1024). Stage base twiddles need only k<512.
__device__ __forceinline__ void fill_twiddles(float2* twq) {
    for (int k = threadIdx.x; k < QUART; k += THREADS) {
        float s, c;
        sincospif((float)k * (1.0f / HALF), &s, &c);
        twq[k] = make_float2(c, s);
    }
}

// 8-point DFT, inverse convention A_q = sum_r a_r e^{+2pi i qr/8}. (Verified R14.)
#define C707 0.70710678118654752440f
__device__ __forceinline__ void dft8_inv(float2* a) {
    float2 b0 = cadd(a[0], a[4]), b1 = csub(a[0], a[4]);
    float2 b2 = cadd(a[2], a[6]), b3 = csub(a[2], a[6]);
    float2 b4 = cadd(a[1], a[5]), b5 = csub(a[1], a[5]);
    float2 b6 = cadd(a[3], a[7]), b7 = csub(a[3], a[7]);
    float2 t;
    float2 c0 = cadd(b0, b2), c2 = csub(b0, b2);
    t = muli(b3);
    float2 c1 = cadd(b1, t),  c3 = csub(b1, t);
    float2 c4 = cadd(b4, b6), c6 = csub(b4, b6);
    t = muli(b7);
    float2 c5 = cadd(b5, t),  c7 = csub(b5, t);
    a[0] = cadd(c0, c4); a[4] = csub(c0, c4);
    t = make_float2(C707 * (c5.x - c5.y), C707 * (c5.x + c5.y));
    a[1] = cadd(c1, t);  a[5] = csub(c1, t);
    t = muli(c6);
    a[2] = cadd(c2, t);  a[6] = csub(c2, t);
    t = make_float2(-C707 * (c7.x + c7.y), C707 * (c7.x - c7.y));
    a[3] = cadd(c3, t);  a[7] = csub(c3, t);
}

// 4 radix-8 DIT inverse stages over SoA shared arrays (digit-reversed input,
// natural output). One butterfly per thread. Twiddle powers built by cmul chain.
__device__ __forceinline__ void radix8_stages(float* bre, float* bim, const float2* twq) {
    const int tid = threadIdx.x;
#pragma unroll
    for (int t3 = 0; t3 < 12; t3 += 3) {     // stage s = t3/3; M = 8^s
        const int M    = 1 << t3;
        const int step = 512 >> t3;
        const int j    = tid & (M - 1);
        const int g    = tid >> t3;
        const int base = (g << (t3 + 3)) + j;
        float2 r[8];
#pragma unroll
        for (int q = 0; q < 8; q++) {
            const int p = IDX(base + q * M);
            r[q] = make_float2(bre[p], bim[p]);
        }
        if (t3 > 0) {
            const float2 w1 = twq[j * step];          // j*step <= 511: direct hit
            const float2 w2 = cmul(w1, w1);
            const float2 w3 = cmul(w2, w1);
            const float2 w4 = cmul(w2, w2);
            const float2 w5 = cmul(w3, w2);
            const float2 w6 = cmul(w3, w3);
            const float2 w7 = cmul(w4, w3);
            r[1] = cmul(r[1], w1); r[2] = cmul(r[2], w2); r[3] = cmul(r[3], w3);
            r[4] = cmul(r[4], w4); r[5] = cmul(r[5], w5); r[6] = cmul(r[6], w6);
            r[7] = cmul(r[7], w7);
        }
        dft8_inv(r);
#pragma unroll
        for (int q = 0; q < 8; q++) {
            const int p = IDX(base + q * M);
            bre[p] = r[q].x; bim[p] = r[q].y;
        }
        __syncthreads();
    }
}

// Kernel 1: reflect-pad signal b, forward FFT via conj(ifft(real)), store g_xh[b].
// Assembly writes directly into digit-reversed slots (bit-permuted thread map).
__global__ void __launch_bounds__(THREADS) cwt_fwd_kernel(const float* __restrict__ x) {
    __shared__ float  bre[IDX(UP - 1) + 1];
    __shared__ float  bim[IDX(UP - 1) + 1];
    __shared__ float2 twq[QUART];

    const int b   = blockIdx.x;
    const int tid = threadIdx.x;
    const unsigned xbase = (unsigned)b * SIGL;

    fill_twiddles(twq);
    for (int t = tid; t < UP; t += THREADS) {
        // lane bits -> i0 (3b) and i3-low (2b) so digit-reversed writes are <=2-way
        const int i0 = t & 7, i3 = (t >> 3) & 7, i1 = (t >> 6) & 7, i2 = (t >> 9) & 7;
        const int i = i0 | (i1 << 3) | (i2 << 6) | (i3 << 9);
        int src;
        if (i < N1)             src = N1 - i;
        else if (i < N1 + SIGL) src = i - N1;
        else                    src = 5118 - i;
        const int p = IDX((i0 << 9) | (i1 << 6) | (i2 << 3) | i3);
        bre[p] = x[xbase + (unsigned)src];
        bim[p] = 0.0f;
    }
    __syncthreads();

    radix8_stages(bre, bim, twq);

    // fft(real x) = conj(ifft_unscaled(x))
    float2* dst = g_xh + (size_t)b * UP;
    for (int i = tid; i < UP; i += THREADS)
        dst[i] = make_float2(bre[IDX(i)], -bim[IDX(i)]);
}

// Kernel 2: block (ap, b): scales a0=2ap, a1=2ap+1 via Hermitian packing.
// Spectrum assembled straight into digit-reversed slots; radix-8 IFFT; crop.
__global__ void __launch_bounds__(THREADS) cwt_main_kernel(const float* __restrict__ psih,
                                                           float* __restrict__ out,
                                                           unsigned o_lim) {
    __shared__ float  bre[IDX(UP - 1) + 1];
    __shared__ float  bim[IDX(UP - 1) + 1];
    __shared__ float2 twq[QUART];

    const int ap  = blockIdx.x;
    const int b   = blockIdx.y;
    const int tid = threadIdx.x;
    const int a0  = 2 * ap;

    fill_twiddles(twq);

    const float*  Pa = psih + (size_t)a0 * UP;
    const float*  Pb = Pa + UP;
    const float2* X  = g_xh + (size_t)b * UP;

    // Z[k] = X[k]*(Pa+iPb)[k]; Z[4096-k] = conj(X[k])*(Pa+iPb)[k]; Z[0]=Z[2048]=0.
    for (int hh = tid; hh < HALF; hh += THREADS) {
        if (hh == 0) {
            bre[IDX(0)] = 0.0f; bim[IDX(0)] = 0.0f;     // rev(0)    = 0
            bre[IDX(4)] = 0.0f; bim[IDX(4)] = 0.0f;     // rev(2048) = 4
            continue;
        }
        const int k0 = hh & 7, k3 = (hh >> 3) & 3, k1 = (hh >> 5) & 7, k2 = (hh >> 8) & 7;
        const int k = k0 | (k1 << 3) | (k2 << 6) | (k3 << 9);     // k in [1,2047]
        const float2 xv = X[k];
        const float2 C  = make_float2(Pa[k], Pb[k]);
        const float2 zl = cmul(xv, C);
        const float2 zu = cmul(make_float2(xv.x, -xv.y), C);
        const int pl = IDX((k0 << 9) | (k1 << 6) | (k2 << 3) | k3);        // rev(k)
        const int n  = UP - k;
        const int pu = IDX(((n & 7) << 9) | (((n >> 3) & 7) << 6) |
                           (((n >> 6) & 7) << 3) | ((n >> 9) & 7));        // rev(n)
        bre[pl] = zl.x; bim[pl] = zl.y;
        bre[pu] = zu.x; bim[pu] = zu.y;
    }
    __syncthreads();

    radix8_stages(bre, bim, twq);

    // Re -> row a0, Im -> row a1. Scale 1/8192 = 1/2 (Hermitian) * 1/4096 (ifft).
    const float inv = 1.0f / 8192.0f;
    const unsigned ob0 = ((unsigned)b * NA + (unsigned)a0) * SIGL;
    const unsigned ob1 = ob0 + SIGL;
    for (int n = tid; n < SIGL; n += THREADS) {
        const int p = IDX(N1 + n);
        const unsigned o0 = ob0 + (unsigned)n;
        const unsigned o1 = ob1 + (unsigned)n;
        if (o0 < o_lim) out[o0] = bre[p] * inv;
        if (o1 < o_lim) out[o1] = bim[p] * inv;
    }
}

extern "C" void kernel_launch(void* const* d_in, const int* in_sizes, int n_in,
                              void* d_out, int out_size) {
    // Confirmed contract (R9 diag): in[0]=x (65536), in[1]=Psih (1048576),
    // out = 16777216 float32 (real part). Order-robust dispatch kept.
    int xi = 0, pi = 1;
    if (n_in >= 2 && in_sizes[0] >= in_sizes[1]) { pi = 0; xi = 1; }
    const float* x    = (const float*)d_in[xi];
    const float* psih = (const float*)d_in[pi];
    float* out = (float*)d_out;

    unsigned o_lim = (unsigned)out_size;
    if (o_lim > (unsigned)OUT_ELEMS) o_lim = (unsigned)OUT_ELEMS;

    cwt_fwd_kernel<<<NB, THREADS>>>(x);
    cwt_main_kernel<<<dim3(NA / 2, NB), THREADS>>>(psih, out, o_lim);
}

// round 17
// speedup vs baseline: 1.6703x; 1.6703x over previous
#include <cuda_runtime.h>

#define UP      4096
#define HALF    2048
#define QUART   1024
#define LOG2UP  12
#define NB      32
#define NA      256
#define SIGL    2048
#define N1      1024
#define THREADS 256          // main kernel (R14 layout depends on this)
#define TFWD    1024         // fwd kernel
#define OUT_ELEMS (NB * NA * SIGL)
#define IDX(i) ((i) + ((i) >> 3))   // float2-granular pad (R14-proven)

// Forward-FFT results: (32, 4096) complex64, natural order. 1 MB static scratch.
__device__ float2 g_xh[NB * UP];

__device__ __forceinline__ float2 cmul(float2 a, float2 b) {
    return make_float2(a.x * b.x - a.y * b.y, a.x * b.y + a.y * b.x);
}
__device__ __forceinline__ float2 cadd(float2 a, float2 b) { return make_float2(a.x + b.x, a.y + b.y); }
__device__ __forceinline__ float2 csub(float2 a, float2 b) { return make_float2(a.x - b.x, a.y - b.y); }
__device__ __forceinline__ float2 muli(float2 a)  { return make_float2(-a.y, a.x); }

// twq[k] = e^{+2*pi*i*k/4096}, k in [0,1024)
__device__ __forceinline__ void fill_twiddles(float2* twq) {
    for (int k = threadIdx.x; k < QUART; k += blockDim.x) {
        float s, c;
        sincospif((float)k * (1.0f / HALF), &s, &c);
        twq[k] = make_float2(c, s);
    }
}

// ---------- verified radix-2 FFT (fwd kernel only; blockDim-agnostic) ----------
template <bool INVERSE>
__device__ void fft_shared_r2(float2* buf, const float2* twq) {
    const int tid = threadIdx.x;
    const int bs  = blockDim.x;
    for (int i = tid; i < UP; i += bs) {
        int j = (int)(__brev((unsigned)i) >> (32 - LOG2UP));
        if (j > i) { float2 t = buf[i]; buf[i] = buf[j]; buf[j] = t; }
    }
    __syncthreads();
    for (int len = 2; len <= UP; len <<= 1) {
        const int half = len >> 1;
        const int step = UP / len;
        for (int t = tid; t < HALF; t += bs) {
            const int j = t & (half - 1);
            const int i = ((t & ~(half - 1)) << 1) | j;
            const int m = j * step;
            const float2 q = twq[m & (QUART - 1)];
            float2 w = (m & QUART) ? muli(q) : q;
            if (!INVERSE) w.y = -w.y;
            const float2 u = buf[i];
            const float2 v = cmul(buf[i + half], w);
            buf[i]        = cadd(u, v);
            buf[i + half] = csub(u, v);
        }
        __syncthreads();
    }
}

// Kernel 1 (verified): reflect-pad signal b, forward FFT, natural-order g_xh[b].
__global__ void __launch_bounds__(TFWD) cwt_fwd_kernel(const float* __restrict__ x) {
    __shared__ float2 buf[UP];
    __shared__ float2 twq[QUART];
    const int b   = blockIdx.x;
    const int tid = threadIdx.x;
    const unsigned xbase = (unsigned)b * SIGL;

    for (int i = tid; i < UP; i += TFWD) {
        int src;
        if (i < N1)             src = N1 - i;
        else if (i < N1 + SIGL) src = i - N1;
        else                    src = 5118 - i;
        buf[i] = make_float2(x[xbase + (unsigned)src], 0.0f);
    }
    fill_twiddles(twq);
    __syncthreads();

    fft_shared_r2<false>(buf, twq);

    float2* dst = g_xh + (size_t)b * UP;
    for (int i = tid; i < UP; i += TFWD) dst[i] = buf[i];
}

// 8-point DFT, inverse convention A_q = sum_r a_r e^{+2pi i qr/8}. (Verified.)
#define C707 0.70710678118654752440f
__device__ __forceinline__ void dft8_inv(float2* a) {
    float2 b0 = cadd(a[0], a[4]), b1 = csub(a[0], a[4]);
    float2 b2 = cadd(a[2], a[6]), b3 = csub(a[2], a[6]);
    float2 b4 = cadd(a[1], a[5]), b5 = csub(a[1], a[5]);
    float2 b6 = cadd(a[3], a[7]), b7 = csub(a[3], a[7]);
    float2 t;
    float2 c0 = cadd(b0, b2), c2 = csub(b0, b2);
    t = muli(b3);
    float2 c1 = cadd(b1, t),  c3 = csub(b1, t);
    float2 c4 = cadd(b4, b6), c6 = csub(b4, b6);
    t = muli(b7);
    float2 c5 = cadd(b5, t),  c7 = csub(b5, t);
    a[0] = cadd(c0, c4); a[4] = csub(c0, c4);
    t = make_float2(C707 * (c5.x - c5.y), C707 * (c5.x + c5.y));
    a[1] = cadd(c1, t);  a[5] = csub(c1, t);
    t = muli(c6);
    a[2] = cadd(c2, t);  a[6] = csub(c2, t);
    t = make_float2(-C707 * (c7.x + c7.y), C707 * (c7.x - c7.y));
    a[3] = cadd(c3, t);  a[7] = csub(c3, t);
}

// Build w^2..w^7 from w^1 and multiply r[1..7] (register chain; no smem).
__device__ __forceinline__ void apply_twiddle_powers(float2* r, float2 w1) {
    const float2 w2 = cmul(w1, w1);
    const float2 w3 = cmul(w2, w1);
    const float2 w4 = cmul(w2, w2);
    const float2 w5 = cmul(w3, w2);
    const float2 w6 = cmul(w3, w3);
    const float2 w7 = cmul(w4, w3);
    r[1] = cmul(r[1], w1); r[2] = cmul(r[2], w2); r[3] = cmul(r[3], w3);
    r[4] = cmul(r[4], w4); r[5] = cmul(r[5], w5); r[6] = cmul(r[6], w6);
    r[7] = cmul(r[7], w7);
}

// Kernel 2 (R14 layout + reg twiddles + fused final stage):
// block (ap, b): scales a0=2ap, a1=2ap+1 via Hermitian packing; radix-8 IFFT.
__global__ void __launch_bounds__(THREADS) cwt_main_kernel(const float* __restrict__ psih,
                                                           float* __restrict__ out,
                                                           unsigned o_lim) {
    __shared__ float2 buf[UP + (UP >> 3)];
    __shared__ float2 twq[QUART];

    const int ap  = blockIdx.x;
    const int b   = blockIdx.y;
    const int tid = threadIdx.x;
    const int a0  = 2 * ap;

    fill_twiddles(twq);

    // ---- spectrum assembly (natural order; linear writes, clean banks) ----
    const float*  Pa = psih + (size_t)a0 * UP;
    const float*  Pb = Pa + UP;
    const float2* X  = g_xh + (size_t)b * UP;
    if (tid == 0) { buf[IDX(0)] = make_float2(0.f, 0.f); buf[IDX(HALF)] = make_float2(0.f, 0.f); }
    for (int k = 1 + tid; k < HALF; k += THREADS) {
        const float2 xv = X[k];
        const float2 C  = make_float2(Pa[k], Pb[k]);
        buf[IDX(k)]      = cmul(xv, C);
        buf[IDX(UP - k)] = cmul(make_float2(xv.x, -xv.y), C);
    }
    __syncthreads();

    // ---- octal digit-reversal permutation (R14-proven) ----
    for (int i = tid; i < UP; i += THREADS) {
        const int j = ((i & 7) << 9) | (((i >> 3) & 7) << 6) | (((i >> 6) & 7) << 3) | ((i >> 9) & 7);
        if (j > i) { float2 t = buf[IDX(i)]; buf[IDX(i)] = buf[IDX(j)]; buf[IDX(j)] = t; }
    }
    __syncthreads();

    // ---- stages 0..2 in shared (register twiddle powers; w1 index < 512 always) ----
#pragma unroll
    for (int t3 = 0; t3 < 9; t3 += 3) {
        const int M    = 1 << t3;
        const int step = 512 >> t3;
#pragma unroll
        for (int h = 0; h < 2; h++) {
            const int u    = tid + h * THREADS;
            const int j    = u & (M - 1);
            const int g    = u >> t3;
            const int base = (g << (t3 + 3)) + j;
            float2 r[8];
#pragma unroll
            for (int q = 0; q < 8; q++) r[q] = buf[IDX(base + q * M)];
            if (t3 > 0) apply_twiddle_powers(r, twq[j * step]);
            dft8_inv(r);
#pragma unroll
            for (int q = 0; q < 8; q++) buf[IDX(base + q * M)] = r[q];
        }
        __syncthreads();
    }

    // ---- final stage (M=512): outputs are natural positions u+512q; crop needs
    //      q in {2..5} -> write those 4 straight to gmem (coalesced), skip STS+crop ----
    const float inv = 1.0f / 8192.0f;    // 1/2 (Hermitian) * 1/4096 (ifft)
    const unsigned ob0 = ((unsigned)b * NA + (unsigned)a0) * SIGL;
    const unsigned ob1 = ob0 + SIGL;
#pragma unroll
    for (int h = 0; h < 2; h++) {
        const int u = tid + h * THREADS;           // j = u, g = 0, base = u
        float2 r[8];
#pragma unroll
        for (int q = 0; q < 8; q++) r[q] = buf[IDX(u + (q << 9))];
        apply_twiddle_powers(r, twq[u]);           // u < 512: direct hit
        dft8_inv(r);
#pragma unroll
        for (int q = 2; q <= 5; q++) {             // n4096 = u + 512q in [1024,3072)
            const unsigned n = (unsigned)u + ((unsigned)(q - 2) << 9);
            const unsigned o0 = ob0 + n;
            const unsigned o1 = ob1 + n;
            if (o0 < o_lim) out[o0] = r[q].x * inv;
            if (o1 < o_lim) out[o1] = r[q].y * inv;
        }
    }
}

extern "C" void kernel_launch(void* const* d_in, const int* in_sizes, int n_in,
                              void* d_out, int out_size) {
    // Confirmed contract (R9 diag): in[0]=x (65536), in[1]=Psih (1048576),
    // out = 16777216 float32 (real part). Order-robust dispatch kept.
    int xi = 0, pi = 1;
    if (n_in >= 2 && in_sizes[0] >= in_sizes[1]) { pi = 0; xi = 1; }
    const float* x    = (const float*)d_in[xi];
    const float* psih = (const float*)d_in[pi];
    float* out = (float*)d_out;

    unsigned o_lim = (unsigned)out_size;
    if (o_lim > (unsigned)OUT_ELEMS) o_lim = (unsigned)OUT_ELEMS;

    cwt_fwd_kernel<<<NB, TFWD>>>(x);
    cwt_main_kernel<<<dim3(NA / 2, NB), THREADS>>>(psih, out, o_lim);
}